// round 16
// baseline (speedup 1.0000x reference)
#include <cuda_runtime.h>
#include <cuda_bf16.h>
#include <cuda_fp16.h>
#include <stdint.h>
#include <math.h>

// lpLSTM: T=512, B=64, IN=H=1024.
// Output: outs [512,64,1024] ++ h_T [1,64,1024] ++ c_T [1,64,1024] (float32)

#define T_STEPS 512
#define BATCH   64
#define INDIM   1024
#define HDIM    1024
#define CTAS    128

// ---------------- scratch (static device memory; allowed) ----------------
__device__ float g_G[4ULL * T_STEPS * BATCH * HDIM];              // 512 MB
__device__ unsigned g_arrive[CTAS];                               // per-CTA arrive slots
__device__ unsigned g_go;                                         // broadcast release
__device__ __half g_Xfp[(size_t)T_STEPS * BATCH * INDIM];         // X fp16, 64 MB
__device__ __half g_Wxfp[4ULL * HDIM * INDIM];                    // x-weights fp16 [g][n][k]
__device__ __half g_Whfp[4ULL * HDIM * INDIM];                    // recurrent fp16 [g][n][k]
__device__ __half g_hfp[2][BATCH * HDIM];                         // h state fp16, dbuf

// ---------------- PTX helpers (sm_80-compatible) ----------------
__device__ __forceinline__ uint32_t smem_u32(const void* p) {
    uint32_t a;
    asm("{ .reg .u64 t; cvta.to.shared.u64 t, %1; cvt.u32.u64 %0, t; }" : "=r"(a) : "l"(p));
    return a;
}
#define CP_ASYNC16(sa, gp) \
    asm volatile("cp.async.cg.shared.global [%0], [%1], 16;" :: "r"(sa), "l"(gp))
#define CP_COMMIT() asm volatile("cp.async.commit_group;" ::: "memory")
#define CP_WAIT(n)  asm volatile("cp.async.wait_group %0;" :: "n"(n) : "memory")

#define LDSM_X4(r0, r1, r2, r3, a) \
    asm volatile("ldmatrix.sync.aligned.m8n8.x4.shared.b16 {%0,%1,%2,%3}, [%4];" \
        : "=r"(r0), "=r"(r1), "=r"(r2), "=r"(r3) : "r"(a))
#define LDSM_X2(r0, r1, a) \
    asm volatile("ldmatrix.sync.aligned.m8n8.x2.shared.b16 {%0,%1}, [%2];" \
        : "=r"(r0), "=r"(r1) : "r"(a))
#define MMA16816H(d, a, b) \
    asm volatile("mma.sync.aligned.m16n8k16.row.col.f32.f16.f16.f32 " \
        "{%0,%1,%2,%3},{%4,%5,%6,%7},{%8,%9},{%0,%1,%2,%3};" \
        : "+f"((d)[0]), "+f"((d)[1]), "+f"((d)[2]), "+f"((d)[3]) \
        : "r"((a)[0]), "r"((a)[1]), "r"((a)[2]), "r"((a)[3]), "r"((b)[0]), "r"((b)[1]))

__device__ __forceinline__ void wait_flag_ge(const unsigned* fp, unsigned tgt) {
    unsigned v;
    do {
        asm volatile("ld.acquire.gpu.u32 %0, [%1];" : "=r"(v) : "l"(fp));
        if (v < tgt) __nanosleep(20);
    } while (v < tgt);
}
__device__ __forceinline__ void store_flag_release(unsigned* fp, unsigned v) {
    asm volatile("st.release.gpu.u32 [%0], %1;" :: "l"(fp), "r"(v) : "memory");
}

// ---------------------------------------------------------------------------
// Prep 1: convert X to fp16
// ---------------------------------------------------------------------------
__global__ __launch_bounds__(256) void xhalf_kernel(const float* __restrict__ X) {
    size_t i = (size_t)blockIdx.x * blockDim.x + threadIdx.x;   // over float4s
    float4 v = ((const float4*)X)[i];
    __half2* p = (__half2*)g_Xfp;
    p[2 * i]     = __floats2half2_rn(v.x, v.y);
    p[2 * i + 1] = __floats2half2_rn(v.z, v.w);
}

// ---------------------------------------------------------------------------
// Prep 2: transpose W [K,H] -> [N][K], convert to fp16 (generic dst)
// ---------------------------------------------------------------------------
__global__ void wprep_kernel(const float* __restrict__ Wi, const float* __restrict__ Wf,
                             const float* __restrict__ Wo, const float* __restrict__ Wc,
                             __half* __restrict__ dst) {
    __shared__ float tile[32][33];
    const int g = blockIdx.z;
    const float* W = (g == 0) ? Wi : (g == 1) ? Wf : (g == 2) ? Wo : Wc;
    const int n  = blockIdx.x * 32 + threadIdx.x;
    const int k0 = blockIdx.y * 32;
#pragma unroll
    for (int i = 0; i < 32; i += 8)
        tile[threadIdx.y + i][threadIdx.x] = W[(size_t)(k0 + threadIdx.y + i) * HDIM + n];
    __syncthreads();
    const int kk = k0 + threadIdx.x;
    const int nn = blockIdx.x * 32 + threadIdx.y;
#pragma unroll
    for (int i = 0; i < 32; i += 8) {
        float v = tile[threadIdx.x][threadIdx.y + i];
        dst[(size_t)g * HDIM * INDIM + (size_t)(nn + i) * INDIM + kk] = __float2half_rn(v);
    }
}

// ---------------------------------------------------------------------------
// Kernel 1: x-projection via single-term fp16 HMMA (exact R11 config:
// 128x128 CTA tile, 8 warps, BK=32, 2-stage cp.async, 2 CTAs/SM).
// ---------------------------------------------------------------------------
#define XP_BK      32
#define XP_NCHUNK  (INDIM / XP_BK)
#define XP_STRIDE  40
#define XP_MATSZ   (128 * XP_STRIDE * 2)   // 10240
#define XP_STAGE   (2 * XP_MATSZ)          // 20480
#define XP_SMEM    (2 * XP_STAGE)          // 40960

__global__ __launch_bounds__(256) void xproj_mma_kernel(
    const float* __restrict__ bi, const float* __restrict__ bf_,
    const float* __restrict__ bo, const float* __restrict__ bc)
{
    extern __shared__ char smem[];
    const uint32_t sb = smem_u32(smem);
    const int g   = blockIdx.z;
    const int n0  = blockIdx.x * 128;
    const int m0  = blockIdx.y * 128;
    const int tid = threadIdx.x;
    const int wid = tid >> 5;
    const int lane = tid & 31;
    const int warp_m = (wid >> 2) * 64;
    const int warp_n = (wid & 3) * 32;

    const float* bias = (g == 0) ? bi : (g == 1) ? bf_ : (g == 2) ? bo : bc;
    const __half* Xf = g_Xfp;
    const __half* Wf = g_Wxfp + (size_t)g * HDIM * INDIM;

    const int lr  = tid >> 2;
    const int lsg = tid & 3;

    float a_cc[4][4][4];
#pragma unroll
    for (int mi = 0; mi < 4; mi++)
#pragma unroll
        for (int ni = 0; ni < 4; ni++)
#pragma unroll
            for (int q = 0; q < 4; q++) a_cc[mi][ni][q] = 0.0f;

    auto load_chunk = [&](int kc, int stg) {
        const int kg = kc * XP_BK;
        const uint32_t base = sb + stg * XP_STAGE;
#pragma unroll
        for (int j = 0; j < 2; j++) {
            const int r = lr + j * 64;
            const uint32_t so = (uint32_t)(r * (XP_STRIDE * 2) + lsg * 16);
            CP_ASYNC16(base + so,            Xf + (size_t)(m0 + r) * INDIM + kg + lsg * 8);
            CP_ASYNC16(base + XP_MATSZ + so, Wf + (size_t)(n0 + r) * INDIM + kg + lsg * 8);
        }
        CP_COMMIT();
    };

    load_chunk(0, 0);

    const uint32_t a_row  = (uint32_t)(warp_m + (lane & 15));
    const uint32_t a_coff = (uint32_t)((lane >> 4) * 8);
    const uint32_t b_row0 = (uint32_t)(warp_n + (lane & 7));
    const uint32_t b_coff = (uint32_t)(((lane >> 3) & 1) * 8);

    for (int kc = 0; kc < XP_NCHUNK; kc++) {
        const int stg = kc & 1;
        if (kc + 1 < XP_NCHUNK) { load_chunk(kc + 1, stg ^ 1); CP_WAIT(1); }
        else                    { CP_WAIT(0); }
        __syncthreads();

        const uint32_t base = sb + stg * XP_STAGE;
#pragma unroll
        for (int ks = 0; ks < 2; ks++) {
            uint32_t ah[4][4], bh[4][2];
#pragma unroll
            for (int mi = 0; mi < 4; mi++) {
                uint32_t addr = base +
                    (a_row + mi * 16) * (XP_STRIDE * 2) + (ks * 16 + a_coff) * 2;
                LDSM_X4(ah[mi][0], ah[mi][1], ah[mi][2], ah[mi][3], addr);
            }
#pragma unroll
            for (int ni = 0; ni < 4; ni++) {
                uint32_t addr = base + XP_MATSZ +
                    (b_row0 + ni * 8) * (XP_STRIDE * 2) + (ks * 16 + b_coff) * 2;
                LDSM_X2(bh[ni][0], bh[ni][1], addr);
            }
#pragma unroll
            for (int mi = 0; mi < 4; mi++)
#pragma unroll
                for (int ni = 0; ni < 4; ni++)
                    MMA16816H(a_cc[mi][ni], ah[mi], bh[ni]);
        }
        __syncthreads();
    }

    float* Gg = g_G + (size_t)g * T_STEPS * BATCH * HDIM;
    const int col_base = n0 + warp_n + 2 * (lane & 3);
    const int row_base = m0 + warp_m + (lane >> 2);
    float bv0[4], bv1[4];
#pragma unroll
    for (int ni = 0; ni < 4; ni++) {
        bv0[ni] = __ldg(bias + col_base + ni * 8);
        bv1[ni] = __ldg(bias + col_base + ni * 8 + 1);
    }
#pragma unroll
    for (int mi = 0; mi < 4; mi++) {
        const int r0 = row_base + mi * 16;
#pragma unroll
        for (int ni = 0; ni < 4; ni++) {
            const int c = col_base + ni * 8;
            float2 v0 = make_float2(a_cc[mi][ni][0] + bv0[ni], a_cc[mi][ni][1] + bv1[ni]);
            float2 v1 = make_float2(a_cc[mi][ni][2] + bv0[ni], a_cc[mi][ni][3] + bv1[ni]);
            *(float2*)(Gg + (size_t)r0 * HDIM + c)       = v0;
            *(float2*)(Gg + (size_t)(r0 + 8) * HDIM + c) = v1;
        }
    }
}

// ---------------------------------------------------------------------------
// Kernel 2: persistent tensor-core recurrence (exact R11 datapath), with a
// COLLECTOR-BROADCAST barrier: each CTA releases its own arrive slot (no
// atomics, no contention); CTA0's threads 0-127 poll one slot each, then
// tid0 releases g_go; other CTAs poll only g_go. Monotonic values, no reset.
// smem: W(66048) | staging 2x17408 / partials 40960 (aliased) = 107008 B.
// ---------------------------------------------------------------------------
#define SC_NT      256
#define SC_WSTRIDE 1032
#define SC_WMAT    (32 * SC_WSTRIDE * 2)      // 66048
#define SC_HBASE   SC_WMAT                    // 66048
#define SC_HSTRIDE 136
#define SC_HMAT    (64 * SC_HSTRIDE * 2)      // 17408
#define SC_PSTRIDE 40
#define SC_PK      (64 * SC_PSTRIDE)          // 2560 floats per k-partial
#define SC_PBYTES  (4 * SC_PK * 4)            // 40960
#define SC_SMEM    (SC_HBASE + SC_PBYTES)     // 107008

__global__ __launch_bounds__(SC_NT, 1) void scan_mma_kernel(
    const float* __restrict__ ret,
    const float* __restrict__ h0,
    const float* __restrict__ c0,
    float* __restrict__ out)
{
    extern __shared__ char smem[];
    const uint32_t sb = smem_u32(smem);
    const int tid  = threadIdx.x;
    const int wid  = tid >> 5;
    const int lane = tid & 31;
    const int hbase = blockIdx.x * 8;
    const int w_mi = wid & 1;       // m-half
    const int w_ki = wid >> 1;      // k-quarter

    // ---- load recurrent weights (single fp16) into smem once ----
    for (int i = tid; i < 32 * 128; i += SC_NT) {
        int lr = i >> 7, seg = i & 127;
        int g = lr >> 3, j = lr & 7;
        const __half* sp = g_Whfp + ((size_t)g * HDIM + hbase + j) * INDIM + seg * 8;
        CP_ASYNC16(sb + lr * (SC_WSTRIDE * 2) + seg * 16, sp);
    }
    CP_COMMIT();
    CP_WAIT(0);

    // ---- per-thread elementwise state: two (b,h) pairs ----
    const int b_0 = tid >> 3, hl0 = tid & 7;          // b 0..31
    const int b_1 = b_0 + 32;                          // b 32..63
    const int hc = hbase + hl0;
    const size_t ix0 = (size_t)b_0 * HDIM + hc;
    const size_t ix1 = (size_t)b_1 * HDIM + hc;
    float cr0 = c0[ix0], cr1 = c0[ix1];
    float hp0 = h0[ix0], hp1 = h0[ix1];
    const float rr0 = ret[hc];

    // publish h(0) into buffer 0 (own cols only)
    g_hfp[0][ix0] = __float2half_rn(hp0);
    g_hfp[0][ix1] = __float2half_rn(hp1);

    // ---- collector-broadcast global barrier ----
    unsigned nbar = 0;
#define GBAR() do { nbar++; __threadfence(); __syncthreads(); \
    if (tid == 0) store_flag_release(&g_arrive[blockIdx.x], nbar); \
    if (blockIdx.x == 0) { \
        if (tid < CTAS) wait_flag_ge(&g_arrive[tid], nbar); \
        __syncthreads(); \
        if (tid == 0) store_flag_release(&g_go, nbar); \
    } else { \
        if (tid == 0) wait_flag_ge(&g_go, nbar); \
        __syncthreads(); \
    } } while (0)

    GBAR();  // h(0) visible everywhere; weights loaded

    // stage chunk c of h: 64 rows x 128 cols fp16
    auto load_hchunk = [&](int c, int buf, const __half* H) {
        const uint32_t hb = sb + SC_HBASE + buf * SC_HMAT;
#pragma unroll
        for (int j = 0; j < 4; j++) {
            int i = j * SC_NT + tid;
            int row = i >> 4, seg = i & 15;
            CP_ASYNC16(hb + row * (SC_HSTRIDE * 2) + seg * 16,
                       H + (size_t)row * HDIM + c * 128 + seg * 8);
        }
        CP_COMMIT();
    };

    const size_t plane = (size_t)T_STEPS * BATCH * HDIM;
    float* P = (float*)(smem + SC_HBASE);   // partials alias staging region

    const uint32_t a_rl   = (uint32_t)(w_mi * 32 + (lane & 15));
    const uint32_t a_koff = (uint32_t)((lane >> 4) * 8);
    const uint32_t b_rl   = (uint32_t)(lane & 7);
    const uint32_t b_koff = (uint32_t)(((lane >> 3) & 3) * 8);

    for (int t = 0; t < T_STEPS; t++) {
        const __half* H = g_hfp[t & 1];

        const float* Gt = g_G + (size_t)t * BATCH * HDIM;
        float G00 = Gt[0 * plane + ix0], G01 = Gt[1 * plane + ix0];
        float G02 = Gt[2 * plane + ix0], G03 = Gt[3 * plane + ix0];
        float G10 = Gt[0 * plane + ix1], G11 = Gt[1 * plane + ix1];
        float G12 = Gt[2 * plane + ix1], G13 = Gt[3 * plane + ix1];

        float dacc[2][4][4];
#pragma unroll
        for (int mt = 0; mt < 2; mt++)
#pragma unroll
            for (int ni = 0; ni < 4; ni++)
#pragma unroll
                for (int q = 0; q < 4; q++) dacc[mt][ni][q] = 0.0f;

        load_hchunk(0, 0, H);
        for (int c = 0; c < 8; c++) {
            const int buf = c & 1;
            if (c < 7) { load_hchunk(c + 1, buf ^ 1, H); CP_WAIT(1); }
            else       { CP_WAIT(0); }
            __syncthreads();

            const uint32_t hb = sb + SC_HBASE + buf * SC_HMAT;
            // B fragments: 4 gates, warp's k32 slice (single fp16)
            uint32_t bh[4][4];
#pragma unroll
            for (int ni = 0; ni < 4; ni++) {
                uint32_t addrB = sb + (ni * 8 + b_rl) * (SC_WSTRIDE * 2)
                    + ((uint32_t)(c * 128) + (uint32_t)(w_ki * 32) + b_koff) * 2;
                LDSM_X4(bh[ni][0], bh[ni][1], bh[ni][2], bh[ni][3], addrB);
            }
#pragma unroll
            for (int kk = 0; kk < 2; kk++) {
                uint32_t ah[2][4];
#pragma unroll
                for (int mt = 0; mt < 2; mt++) {
                    uint32_t addrA = hb + (a_rl + mt * 16) * (SC_HSTRIDE * 2)
                        + ((uint32_t)(w_ki * 32 + kk * 16) + a_koff) * 2;
                    LDSM_X4(ah[mt][0], ah[mt][1], ah[mt][2], ah[mt][3], addrA);
                }
#pragma unroll
                for (int mt = 0; mt < 2; mt++)
#pragma unroll
                    for (int ni = 0; ni < 4; ni++)
                        MMA16816H(dacc[mt][ni], ah[mt], bh[ni] + kk * 2);
            }
            __syncthreads();
        }

        // ---- store per-warp K-partials to P[ki][64][40] ----
        {
            float* Pk = P + w_ki * SC_PK;
            const int arow = lane >> 2;
            const int acol = 2 * (lane & 3);
#pragma unroll
            for (int mt = 0; mt < 2; mt++)
#pragma unroll
                for (int ni = 0; ni < 4; ni++) {
                    float* p0 = Pk + (w_mi * 32 + mt * 16 + arow) * SC_PSTRIDE
                                   + ni * 8 + acol;
                    *(float2*)p0 = make_float2(dacc[mt][ni][0], dacc[mt][ni][1]);
                    float* p1 = p0 + 8 * SC_PSTRIDE;
                    *(float2*)p1 = make_float2(dacc[mt][ni][2], dacc[mt][ni][3]);
                }
        }
        __syncthreads();

        // ---- reduce 4 K-partials + fused LSTM; publish h(t+1) ----
        float* outT = out + (size_t)t * BATCH * HDIM;
        __half* Hn = g_hfp[(t + 1) & 1];
#pragma unroll
        for (int pair = 0; pair < 2; pair++) {
            const int    bb = pair ? b_1 : b_0;
            const size_t ix = pair ? ix1 : ix0;
            float s0 = 0.f, s1 = 0.f, s2 = 0.f, s3 = 0.f;
#pragma unroll
            for (int k = 0; k < 4; k++) {
                const float* Pw = P + k * SC_PK + bb * SC_PSTRIDE + hl0;
                s0 += Pw[0];
                s1 += Pw[8];
                s2 += Pw[16];
                s3 += Pw[24];
            }
            float gi = s0 + (pair ? G10 : G00);
            float gf = s1 + (pair ? G11 : G01);
            float go = s2 + (pair ? G12 : G02);
            float gc = s3 + (pair ? G13 : G03);
            float i_t = 1.0f / (1.0f + __expf(-gi));
            float f_t = 1.0f / (1.0f + __expf(-gf));
            float o_t = 1.0f / (1.0f + __expf(-go));
            float g_t = tanhf(gc);
            float& cr = pair ? cr1 : cr0;
            float& hp = pair ? hp1 : hp0;
            cr = cr * f_t + i_t * g_t;
            float hl_ = o_t * tanhf(cr);
            hp = rr0 * hp + (1.0f - rr0) * hl_;
            outT[ix] = hp;
            Hn[ix] = __float2half_rn(hp);
        }

        GBAR();
    }

    // tail: h_T and c_T
    {
        float* hT = out + (size_t)T_STEPS * BATCH * HDIM;
        float* cT = hT + (size_t)BATCH * HDIM;
        hT[ix0] = hp0; hT[ix1] = hp1;
        cT[ix0] = cr0; cT[ix1] = cr1;
    }
#undef GBAR
}

// ---------------------------------------------------------------------------
extern "C" void kernel_launch(void* const* d_in, const int* in_sizes, int n_in,
                              void* d_out, int out_size)
{
    const float* X    = (const float*)d_in[0];
    const float* h0   = (const float*)d_in[1];
    const float* c0   = (const float*)d_in[2];
    const float* w_xi = (const float*)d_in[3];
    const float* w_xf = (const float*)d_in[4];
    const float* w_xo = (const float*)d_in[5];
    const float* w_xc = (const float*)d_in[6];
    const float* w_hi = (const float*)d_in[7];
    const float* w_hf = (const float*)d_in[8];
    const float* w_ho = (const float*)d_in[9];
    const float* w_hc = (const float*)d_in[10];
    const float* b_i  = (const float*)d_in[11];
    const float* b_f  = (const float*)d_in[12];
    const float* b_o  = (const float*)d_in[13];
    const float* b_c  = (const float*)d_in[14];
    const float* rr   = (const float*)d_in[15];

    float* out = (float*)d_out;

    void* arr_ptr = nullptr;
    void* go_ptr  = nullptr;
    cudaGetSymbolAddress(&arr_ptr, g_arrive);
    cudaGetSymbolAddress(&go_ptr, g_go);
    cudaMemsetAsync(arr_ptr, 0, CTAS * sizeof(unsigned));
    cudaMemsetAsync(go_ptr, 0, sizeof(unsigned));

    void *wxfp, *whfp;
    cudaGetSymbolAddress(&wxfp, g_Wxfp);
    cudaGetSymbolAddress(&whfp, g_Whfp);

    static int attr_set = 0;
    if (!attr_set) {
        cudaFuncSetAttribute(xproj_mma_kernel,
                             cudaFuncAttributeMaxDynamicSharedMemorySize, XP_SMEM);
        cudaFuncSetAttribute(scan_mma_kernel,
                             cudaFuncAttributeMaxDynamicSharedMemorySize, SC_SMEM);
        attr_set = 1;
    }

    // Preps: fp16 conversions (input + both weight sets)
    xhalf_kernel<<<(T_STEPS * BATCH * INDIM) / (4 * 256), 256>>>(X);
    wprep_kernel<<<dim3(32, 32, 4), dim3(32, 8)>>>(
        w_xi, w_xf, w_xo, w_xc, (__half*)wxfp);
    wprep_kernel<<<dim3(32, 32, 4), dim3(32, 8)>>>(
        w_hi, w_hf, w_ho, w_hc, (__half*)whfp);

    // Phase 1: gate preactivations via single-term fp16 HMMA
    {
        dim3 grid(HDIM / 128, (T_STEPS * BATCH) / 128, 4);
        xproj_mma_kernel<<<grid, 256, XP_SMEM>>>(b_i, b_f, b_o, b_c);
    }

    // Phase 2: persistent tensor-core scan (collector-broadcast barrier)
    scan_mma_kernel<<<CTAS, SC_NT, SC_SMEM>>>(rr, h0, c0, out);
}

// round 17
// speedup vs baseline: 1.2757x; 1.2757x over previous
#include <cuda_runtime.h>
#include <cuda_bf16.h>
#include <cuda_fp16.h>
#include <stdint.h>
#include <math.h>

// lpLSTM: T=512, B=64, IN=H=1024.
// Output: outs [512,64,1024] ++ h_T [1,64,1024] ++ c_T [1,64,1024] (float32)

#define T_STEPS 512
#define BATCH   64
#define INDIM   1024
#define HDIM    1024
#define CTAS    128

// ---------------- scratch (static device memory; allowed) ----------------
__device__ float g_G[4ULL * T_STEPS * BATCH * HDIM];              // 512 MB
__device__ unsigned g_bar;
__device__ __half g_Xfp[(size_t)T_STEPS * BATCH * INDIM];         // X fp16, 64 MB
__device__ __half g_Wxfp[4ULL * HDIM * INDIM];                    // x-weights fp16 [g][n][k]
__device__ __half g_Whfp[4ULL * HDIM * INDIM];                    // recurrent fp16 [g][n][k]
__device__ __half g_hfp[2][BATCH * HDIM];                         // h state fp16, dbuf

// ---------------- PTX helpers (sm_80-compatible) ----------------
__device__ __forceinline__ uint32_t smem_u32(const void* p) {
    uint32_t a;
    asm("{ .reg .u64 t; cvta.to.shared.u64 t, %1; cvt.u32.u64 %0, t; }" : "=r"(a) : "l"(p));
    return a;
}
#define CP_ASYNC16(sa, gp) \
    asm volatile("cp.async.cg.shared.global [%0], [%1], 16;" :: "r"(sa), "l"(gp))
#define CP_COMMIT() asm volatile("cp.async.commit_group;" ::: "memory")
#define CP_WAIT(n)  asm volatile("cp.async.wait_group %0;" :: "n"(n) : "memory")

#define LDSM_X4(r0, r1, r2, r3, a) \
    asm volatile("ldmatrix.sync.aligned.m8n8.x4.shared.b16 {%0,%1,%2,%3}, [%4];" \
        : "=r"(r0), "=r"(r1), "=r"(r2), "=r"(r3) : "r"(a))
#define LDSM_X2(r0, r1, a) \
    asm volatile("ldmatrix.sync.aligned.m8n8.x2.shared.b16 {%0,%1}, [%2];" \
        : "=r"(r0), "=r"(r1) : "r"(a))
#define MMA16816H(d, a, b) \
    asm volatile("mma.sync.aligned.m16n8k16.row.col.f32.f16.f16.f32 " \
        "{%0,%1,%2,%3},{%4,%5,%6,%7},{%8,%9},{%0,%1,%2,%3};" \
        : "+f"((d)[0]), "+f"((d)[1]), "+f"((d)[2]), "+f"((d)[3]) \
        : "r"((a)[0]), "r"((a)[1]), "r"((a)[2]), "r"((a)[3]), "r"((b)[0]), "r"((b)[1]))

// ---------------------------------------------------------------------------
// Prep 1: convert X to fp16
// ---------------------------------------------------------------------------
__global__ __launch_bounds__(256) void xhalf_kernel(const float* __restrict__ X) {
    size_t i = (size_t)blockIdx.x * blockDim.x + threadIdx.x;   // over float4s
    float4 v = ((const float4*)X)[i];
    __half2* p = (__half2*)g_Xfp;
    p[2 * i]     = __floats2half2_rn(v.x, v.y);
    p[2 * i + 1] = __floats2half2_rn(v.z, v.w);
}

// ---------------------------------------------------------------------------
// Prep 2: transpose W [K,H] -> [N][K], convert to fp16 (generic dst)
// ---------------------------------------------------------------------------
__global__ void wprep_kernel(const float* __restrict__ Wi, const float* __restrict__ Wf,
                             const float* __restrict__ Wo, const float* __restrict__ Wc,
                             __half* __restrict__ dst) {
    __shared__ float tile[32][33];
    const int g = blockIdx.z;
    const float* W = (g == 0) ? Wi : (g == 1) ? Wf : (g == 2) ? Wo : Wc;
    const int n  = blockIdx.x * 32 + threadIdx.x;
    const int k0 = blockIdx.y * 32;
#pragma unroll
    for (int i = 0; i < 32; i += 8)
        tile[threadIdx.y + i][threadIdx.x] = W[(size_t)(k0 + threadIdx.y + i) * HDIM + n];
    __syncthreads();
    const int kk = k0 + threadIdx.x;
    const int nn = blockIdx.x * 32 + threadIdx.y;
#pragma unroll
    for (int i = 0; i < 32; i += 8) {
        float v = tile[threadIdx.x][threadIdx.y + i];
        dst[(size_t)g * HDIM * INDIM + (size_t)(nn + i) * INDIM + kk] = __float2half_rn(v);
    }
}

// ---------------------------------------------------------------------------
// Kernel 1: x-projection via single-term fp16 HMMA.
// 128x128 CTA tile, 8 warps (2x4), warp tile 64x32, BK=64, 2-stage cp.async.
// Row stride 72 fp16 (144 B) -> conflict-free ldmatrix (bank step 4/row).
// smem: 2 stages x (A 18432 + B 18432) = 73728 B -> 2 CTAs/SM.
// ---------------------------------------------------------------------------
#define XP_BK      64
#define XP_NCHUNK  (INDIM / XP_BK)         // 16
#define XP_STRIDE  72
#define XP_MATSZ   (128 * XP_STRIDE * 2)   // 18432
#define XP_STAGE   (2 * XP_MATSZ)          // 36864
#define XP_SMEM    (2 * XP_STAGE)          // 73728

__global__ __launch_bounds__(256) void xproj_mma_kernel(
    const float* __restrict__ bi, const float* __restrict__ bf_,
    const float* __restrict__ bo, const float* __restrict__ bc)
{
    extern __shared__ char smem[];
    const uint32_t sb = smem_u32(smem);
    const int g   = blockIdx.z;
    const int n0  = blockIdx.x * 128;
    const int m0  = blockIdx.y * 128;
    const int tid = threadIdx.x;
    const int wid = tid >> 5;
    const int lane = tid & 31;
    const int warp_m = (wid >> 2) * 64;
    const int warp_n = (wid & 3) * 32;

    const float* bias = (g == 0) ? bi : (g == 1) ? bf_ : (g == 2) ? bo : bc;
    const __half* Xf = g_Xfp;
    const __half* Wf = g_Wxfp + (size_t)g * HDIM * INDIM;

    // load mapping: 128 rows x 8 segs(16B) = 1024 units, 4 per thread
    const int lrow = tid >> 1;           // rows 0..127 (j adds nothing; see loop)
    (void)lrow;

    float a_cc[4][4][4];
#pragma unroll
    for (int mi = 0; mi < 4; mi++)
#pragma unroll
        for (int ni = 0; ni < 4; ni++)
#pragma unroll
            for (int q = 0; q < 4; q++) a_cc[mi][ni][q] = 0.0f;

    auto load_chunk = [&](int kc, int stg) {
        const int kg = kc * XP_BK;
        const uint32_t base = sb + stg * XP_STAGE;
#pragma unroll
        for (int j = 0; j < 4; j++) {
            int i = j * 256 + tid;        // 0..1023
            int row = i >> 3;             // 0..127
            int seg = i & 7;              // 0..7 (16B each = 8 fp16)
            uint32_t so = (uint32_t)(row * (XP_STRIDE * 2) + seg * 16);
            CP_ASYNC16(base + so,            Xf + (size_t)(m0 + row) * INDIM + kg + seg * 8);
            CP_ASYNC16(base + XP_MATSZ + so, Wf + (size_t)(n0 + row) * INDIM + kg + seg * 8);
        }
        CP_COMMIT();
    };

    load_chunk(0, 0);

    const uint32_t a_row  = (uint32_t)(warp_m + (lane & 15));
    const uint32_t a_coff = (uint32_t)((lane >> 4) * 8);
    const uint32_t b_row0 = (uint32_t)(warp_n + (lane & 7));
    const uint32_t b_coff = (uint32_t)(((lane >> 3) & 1) * 8);

    for (int kc = 0; kc < XP_NCHUNK; kc++) {
        const int stg = kc & 1;
        if (kc + 1 < XP_NCHUNK) { load_chunk(kc + 1, stg ^ 1); CP_WAIT(1); }
        else                    { CP_WAIT(0); }
        __syncthreads();

        const uint32_t base = sb + stg * XP_STAGE;
#pragma unroll
        for (int ks = 0; ks < 4; ks++) {
            uint32_t ah[4][4], bh[4][2];
#pragma unroll
            for (int mi = 0; mi < 4; mi++) {
                uint32_t addr = base +
                    (a_row + mi * 16) * (XP_STRIDE * 2) + (ks * 16 + a_coff) * 2;
                LDSM_X4(ah[mi][0], ah[mi][1], ah[mi][2], ah[mi][3], addr);
            }
#pragma unroll
            for (int ni = 0; ni < 4; ni++) {
                uint32_t addr = base + XP_MATSZ +
                    (b_row0 + ni * 8) * (XP_STRIDE * 2) + (ks * 16 + b_coff) * 2;
                LDSM_X2(bh[ni][0], bh[ni][1], addr);
            }
#pragma unroll
            for (int mi = 0; mi < 4; mi++)
#pragma unroll
                for (int ni = 0; ni < 4; ni++)
                    MMA16816H(a_cc[mi][ni], ah[mi], bh[ni]);
        }
        __syncthreads();
    }

    float* Gg = g_G + (size_t)g * T_STEPS * BATCH * HDIM;
    const int col_base = n0 + warp_n + 2 * (lane & 3);
    const int row_base = m0 + warp_m + (lane >> 2);
    float bv0[4], bv1[4];
#pragma unroll
    for (int ni = 0; ni < 4; ni++) {
        bv0[ni] = __ldg(bias + col_base + ni * 8);
        bv1[ni] = __ldg(bias + col_base + ni * 8 + 1);
    }
#pragma unroll
    for (int mi = 0; mi < 4; mi++) {
        const int r0 = row_base + mi * 16;
#pragma unroll
        for (int ni = 0; ni < 4; ni++) {
            const int c = col_base + ni * 8;
            float2 v0 = make_float2(a_cc[mi][ni][0] + bv0[ni], a_cc[mi][ni][1] + bv1[ni]);
            float2 v1 = make_float2(a_cc[mi][ni][2] + bv0[ni], a_cc[mi][ni][3] + bv1[ni]);
            *(float2*)(Gg + (size_t)r0 * HDIM + c)       = v0;
            *(float2*)(Gg + (size_t)(r0 + 8) * HDIM + c) = v1;
        }
    }
}

// ---------------------------------------------------------------------------
// Kernel 2: persistent tensor-core recurrence, single-term fp16, (2,1,4)
// warp decomposition, atomic-counter barrier (R11 — fastest measured).
// KCHUNK=256: 4 chunks/step (8 syncs instead of 16). Row stride 264 fp16
// (528 B) -> conflict-free ldmatrix family. W stride 1032 unchanged.
// smem: W(66048) + 2 x h-chunk(33792) = 133632; partials alias staging.
// ---------------------------------------------------------------------------
#define SC_NT      256
#define SC_WSTRIDE 1032
#define SC_WMAT    (32 * SC_WSTRIDE * 2)      // 66048
#define SC_HBASE   SC_WMAT                    // 66048
#define SC_HSTRIDE 264
#define SC_HMAT    (64 * SC_HSTRIDE * 2)      // 33792
#define SC_PSTRIDE 40
#define SC_PK      (64 * SC_PSTRIDE)          // 2560 floats per k-partial
#define SC_SMEM    (SC_HBASE + 2 * SC_HMAT)   // 133632 (>= partials 40960)

__global__ __launch_bounds__(SC_NT, 1) void scan_mma_kernel(
    const float* __restrict__ ret,
    const float* __restrict__ h0,
    const float* __restrict__ c0,
    float* __restrict__ out)
{
    extern __shared__ char smem[];
    const uint32_t sb = smem_u32(smem);
    const int tid  = threadIdx.x;
    const int wid  = tid >> 5;
    const int lane = tid & 31;
    const int hbase = blockIdx.x * 8;
    const int w_mi = wid & 1;       // m-half
    const int w_ki = wid >> 1;      // k-quarter (64 wide per 256-chunk)

    // ---- load recurrent weights (single fp16) into smem once ----
    for (int i = tid; i < 32 * 128; i += SC_NT) {
        int lr = i >> 7, seg = i & 127;
        int g = lr >> 3, j = lr & 7;
        const __half* sp = g_Whfp + ((size_t)g * HDIM + hbase + j) * INDIM + seg * 8;
        CP_ASYNC16(sb + lr * (SC_WSTRIDE * 2) + seg * 16, sp);
    }
    CP_COMMIT();
    CP_WAIT(0);

    // ---- per-thread elementwise state: two (b,h) pairs ----
    const int b_0 = tid >> 3, hl0 = tid & 7;          // b 0..31
    const int b_1 = b_0 + 32;                          // b 32..63
    const int hc = hbase + hl0;
    const size_t ix0 = (size_t)b_0 * HDIM + hc;
    const size_t ix1 = (size_t)b_1 * HDIM + hc;
    float cr0 = c0[ix0], cr1 = c0[ix1];
    float hp0 = h0[ix0], hp1 = h0[ix1];
    const float rr0 = ret[hc];

    // publish h(0) into buffer 0 (own cols only)
    g_hfp[0][ix0] = __float2half_rn(hp0);
    g_hfp[0][ix1] = __float2half_rn(hp1);

    unsigned nbar = 0;
#define GBAR() do { nbar++; __threadfence(); __syncthreads(); \
    if (tid == 0) { atomicAdd(&g_bar, 1u); volatile unsigned* _b = &g_bar; \
        while (*_b < nbar * CTAS) { __nanosleep(32); } } \
    __syncthreads(); } while (0)

    GBAR();  // h(0) visible everywhere; weights loaded

    // stage chunk c of h: 64 rows x 256 cols fp16 (2048 x 16B, 8 per thread)
    auto load_hchunk = [&](int c, int buf, const __half* H) {
        const uint32_t hb = sb + SC_HBASE + buf * SC_HMAT;
#pragma unroll
        for (int j = 0; j < 8; j++) {
            int i = j * SC_NT + tid;
            int row = i >> 5, seg = i & 31;
            CP_ASYNC16(hb + row * (SC_HSTRIDE * 2) + seg * 16,
                       H + (size_t)row * HDIM + c * 256 + seg * 8);
        }
        CP_COMMIT();
    };

    const size_t plane = (size_t)T_STEPS * BATCH * HDIM;
    float* P = (float*)(smem + SC_HBASE);   // partials alias staging region

    const uint32_t a_rl   = (uint32_t)(w_mi * 32 + (lane & 15));
    const uint32_t a_koff = (uint32_t)((lane >> 4) * 8);
    const uint32_t b_rl   = (uint32_t)(lane & 7);
    const uint32_t b_koff = (uint32_t)(((lane >> 3) & 3) * 8);

    for (int t = 0; t < T_STEPS; t++) {
        const __half* H = g_hfp[t & 1];

        const float* Gt = g_G + (size_t)t * BATCH * HDIM;
        float G00 = Gt[0 * plane + ix0], G01 = Gt[1 * plane + ix0];
        float G02 = Gt[2 * plane + ix0], G03 = Gt[3 * plane + ix0];
        float G10 = Gt[0 * plane + ix1], G11 = Gt[1 * plane + ix1];
        float G12 = Gt[2 * plane + ix1], G13 = Gt[3 * plane + ix1];

        float dacc[2][4][4];
#pragma unroll
        for (int mt = 0; mt < 2; mt++)
#pragma unroll
            for (int ni = 0; ni < 4; ni++)
#pragma unroll
                for (int q = 0; q < 4; q++) dacc[mt][ni][q] = 0.0f;

        load_hchunk(0, 0, H);
        for (int c = 0; c < 4; c++) {
            const int buf = c & 1;
            if (c < 3) { load_hchunk(c + 1, buf ^ 1, H); CP_WAIT(1); }
            else       { CP_WAIT(0); }
            __syncthreads();

            const uint32_t hb = sb + SC_HBASE + buf * SC_HMAT;
            // B fragments: 4 gates x 2 k32-halves of the warp's 64-wide slice
            uint32_t bh[4][2][4];
#pragma unroll
            for (int ni = 0; ni < 4; ni++)
#pragma unroll
                for (int kb = 0; kb < 2; kb++) {
                    uint32_t addrB = sb + (ni * 8 + b_rl) * (SC_WSTRIDE * 2)
                        + ((uint32_t)(c * 256 + w_ki * 64 + kb * 32) + b_koff) * 2;
                    LDSM_X4(bh[ni][kb][0], bh[ni][kb][1], bh[ni][kb][2], bh[ni][kb][3], addrB);
                }
#pragma unroll
            for (int kk = 0; kk < 4; kk++) {
                uint32_t ah[2][4];
#pragma unroll
                for (int mt = 0; mt < 2; mt++) {
                    uint32_t addrA = hb + (a_rl + mt * 16) * (SC_HSTRIDE * 2)
                        + ((uint32_t)(w_ki * 64 + kk * 16) + a_koff) * 2;
                    LDSM_X4(ah[mt][0], ah[mt][1], ah[mt][2], ah[mt][3], addrA);
                }
                const int kb = kk >> 1, sub = kk & 1;
#pragma unroll
                for (int mt = 0; mt < 2; mt++)
#pragma unroll
                    for (int ni = 0; ni < 4; ni++)
                        MMA16816H(dacc[mt][ni], ah[mt], bh[ni][kb] + sub * 2);
            }
            __syncthreads();
        }

        // ---- store per-warp K-partials to P[ki][64][40] ----
        {
            float* Pk = P + w_ki * SC_PK;
            const int arow = lane >> 2;
            const int acol = 2 * (lane & 3);
#pragma unroll
            for (int mt = 0; mt < 2; mt++)
#pragma unroll
                for (int ni = 0; ni < 4; ni++) {
                    float* p0 = Pk + (w_mi * 32 + mt * 16 + arow) * SC_PSTRIDE
                                   + ni * 8 + acol;
                    *(float2*)p0 = make_float2(dacc[mt][ni][0], dacc[mt][ni][1]);
                    float* p1 = p0 + 8 * SC_PSTRIDE;
                    *(float2*)p1 = make_float2(dacc[mt][ni][2], dacc[mt][ni][3]);
                }
        }
        __syncthreads();

        // ---- reduce 4 K-partials + fused LSTM; publish h(t+1) ----
        float* outT = out + (size_t)t * BATCH * HDIM;
        __half* Hn = g_hfp[(t + 1) & 1];
#pragma unroll
        for (int pair = 0; pair < 2; pair++) {
            const int    bb = pair ? b_1 : b_0;
            const size_t ix = pair ? ix1 : ix0;
            float s0 = 0.f, s1 = 0.f, s2 = 0.f, s3 = 0.f;
#pragma unroll
            for (int k = 0; k < 4; k++) {
                const float* Pw = P + k * SC_PK + bb * SC_PSTRIDE + hl0;
                s0 += Pw[0];
                s1 += Pw[8];
                s2 += Pw[16];
                s3 += Pw[24];
            }
            float gi = s0 + (pair ? G10 : G00);
            float gf = s1 + (pair ? G11 : G01);
            float go = s2 + (pair ? G12 : G02);
            float gc = s3 + (pair ? G13 : G03);
            float i_t = 1.0f / (1.0f + __expf(-gi));
            float f_t = 1.0f / (1.0f + __expf(-gf));
            float o_t = 1.0f / (1.0f + __expf(-go));
            float g_t = tanhf(gc);
            float& cr = pair ? cr1 : cr0;
            float& hp = pair ? hp1 : hp0;
            cr = cr * f_t + i_t * g_t;
            float hl_ = o_t * tanhf(cr);
            hp = rr0 * hp + (1.0f - rr0) * hl_;
            outT[ix] = hp;
            Hn[ix] = __float2half_rn(hp);
        }

        GBAR();
    }

    // tail: h_T and c_T
    {
        float* hT = out + (size_t)T_STEPS * BATCH * HDIM;
        float* cT = hT + (size_t)BATCH * HDIM;
        hT[ix0] = hp0; hT[ix1] = hp1;
        cT[ix0] = cr0; cT[ix1] = cr1;
    }
#undef GBAR
}

// ---------------------------------------------------------------------------
extern "C" void kernel_launch(void* const* d_in, const int* in_sizes, int n_in,
                              void* d_out, int out_size)
{
    const float* X    = (const float*)d_in[0];
    const float* h0   = (const float*)d_in[1];
    const float* c0   = (const float*)d_in[2];
    const float* w_xi = (const float*)d_in[3];
    const float* w_xf = (const float*)d_in[4];
    const float* w_xo = (const float*)d_in[5];
    const float* w_xc = (const float*)d_in[6];
    const float* w_hi = (const float*)d_in[7];
    const float* w_hf = (const float*)d_in[8];
    const float* w_ho = (const float*)d_in[9];
    const float* w_hc = (const float*)d_in[10];
    const float* b_i  = (const float*)d_in[11];
    const float* b_f  = (const float*)d_in[12];
    const float* b_o  = (const float*)d_in[13];
    const float* b_c  = (const float*)d_in[14];
    const float* rr   = (const float*)d_in[15];

    float* out = (float*)d_out;

    void* bar_ptr = nullptr;
    cudaGetSymbolAddress(&bar_ptr, g_bar);
    cudaMemsetAsync(bar_ptr, 0, sizeof(unsigned));

    void *wxfp, *whfp;
    cudaGetSymbolAddress(&wxfp, g_Wxfp);
    cudaGetSymbolAddress(&whfp, g_Whfp);

    static int attr_set = 0;
    if (!attr_set) {
        cudaFuncSetAttribute(xproj_mma_kernel,
                             cudaFuncAttributeMaxDynamicSharedMemorySize, XP_SMEM);
        cudaFuncSetAttribute(scan_mma_kernel,
                             cudaFuncAttributeMaxDynamicSharedMemorySize, SC_SMEM);
        attr_set = 1;
    }

    // Preps: fp16 conversions (input + both weight sets)
    xhalf_kernel<<<(T_STEPS * BATCH * INDIM) / (4 * 256), 256>>>(X);
    wprep_kernel<<<dim3(32, 32, 4), dim3(32, 8)>>>(
        w_xi, w_xf, w_xo, w_xc, (__half*)wxfp);
    wprep_kernel<<<dim3(32, 32, 4), dim3(32, 8)>>>(
        w_hi, w_hf, w_ho, w_hc, (__half*)whfp);

    // Phase 1: gate preactivations via single-term fp16 HMMA (BK=64)
    {
        dim3 grid(HDIM / 128, (T_STEPS * BATCH) / 128, 4);
        xproj_mma_kernel<<<grid, 256, XP_SMEM>>>(b_i, b_f, b_o, b_c);
    }

    // Phase 2: persistent tensor-core scan (KCHUNK=256, atomic barrier)
    scan_mma_kernel<<<CTAS, SC_NT, SC_SMEM>>>(rr, h0, c0, out);
}